// round 16
// baseline (speedup 1.0000x reference)
#include <cuda_runtime.h>
#include <math.h>

#define SEQ   40
#define H     4096
#define OUT   128
#define NBLK  128
#define NTHR  1024
#define JPB   32                  // hidden indices per block (= warps per block)
#define RPB   128                 // rows per block (32 j x 4 gates)
#define ROWS  (4 * H)
#define CH_B  32768               // bytes per chunk (128 rows x 256 cols)
#define NCHUNK 16
#define SCH   6                   // chunks 0..5 resident in smem (192 KB)
#define BLOCK_WQ (RPB * H)        // 512 KB s8 weights per block
#define SMEM_W (SCH * CH_B)

// ---- persistent device state ----
__device__ float    g_h[H];                                      // fp32 h_last for dense
__device__ unsigned g_hq[2][H / 2];                              // ping-pong s16 h (u16[H])
__device__ float    g_scale[ROWS];                               // per-row dequant scale
__device__ __align__(256) unsigned char g_wq[(size_t)NBLK * BLOCK_WQ]; // 67MB s8
__device__ __align__(16) unsigned g_stamp[NBLK];                 // per-block step stamps

// ---------------- quant; paired-row layout (identical to 293us kernel) ----------------
__global__ __launch_bounds__(256) void quant_kernel(const float* __restrict__ w_hh) {
    __shared__ float wmax[8];
    const int r    = blockIdx.x;
    const int tid  = threadIdx.x;
    const int lane = tid & 31, wrp = tid >> 5;

    const float4* rp = (const float4*)(w_hh + (size_t)r * H) + tid * 4;
    const float4 vs[4] = {__ldg(rp), __ldg(rp + 1), __ldg(rp + 2), __ldg(rp + 3)};

    float m = 0.0f;
    #pragma unroll
    for (int q = 0; q < 4; ++q)
        m = fmaxf(m, fmaxf(fmaxf(fabsf(vs[q].x), fabsf(vs[q].y)),
                           fmaxf(fabsf(vs[q].z), fabsf(vs[q].w))));
    #pragma unroll
    for (int o = 16; o > 0; o >>= 1) m = fmaxf(m, __shfl_xor_sync(0xffffffffu, m, o));
    if (lane == 0) wmax[wrp] = m;
    __syncthreads();
    float mx = wmax[0];
    #pragma unroll
    for (int w = 1; w < 8; ++w) mx = fmaxf(mx, wmax[w]);
    if (tid == 0) g_scale[r] = mx * (1.0f / 127.0f);
    const float inv = (mx > 0.0f) ? 127.0f / mx : 0.0f;

    unsigned b[16];
    #pragma unroll
    for (int q = 0; q < 4; ++q) {
        b[4 * q + 0] = __float_as_uint(fmaf(vs[q].x, inv, 8388736.0f));
        b[4 * q + 1] = __float_as_uint(fmaf(vs[q].y, inv, 8388736.0f));
        b[4 * q + 2] = __float_as_uint(fmaf(vs[q].z, inv, 8388736.0f));
        b[4 * q + 3] = __float_as_uint(fmaf(vs[q].w, inv, 8388736.0f));
    }
    uint4 o;
    #pragma unroll
    for (int q = 0; q < 4; ++q) {
        unsigned t0 = __byte_perm(b[4 * q + 0], b[4 * q + 1], 0x0040);
        unsigned t1 = __byte_perm(b[4 * q + 2], b[4 * q + 3], 0x0040);
        ((unsigned*)&o)[q] = __byte_perm(t0, t1, 0x5410) ^ 0x80808080u;
    }
    const int j = r & (H - 1), gate = r >> 12;
    const int B = j >> 5;
    const int wid_ = j & 31;
    const int p = gate >> 1, rp_ = gate & 1;
    const int chunk = tid >> 4;
    const int lpos = (tid & 15) * 2;
    unsigned char* dst = g_wq + (size_t)B * BLOCK_WQ + (size_t)chunk * CH_B
                       + wid_ * 1024 + p * 512 + rp_ * 8;
    *(uint2*)(dst + lpos * 16)       = make_uint2(o.x, o.y);
    *(uint2*)(dst + (lpos + 1) * 16) = make_uint2(o.z, o.w);
}

__device__ __forceinline__ int dp4a_us(unsigned a, unsigned b, int c) {
    int d; asm("dp4a.u32.s32 %0, %1, %2, %3;" : "=r"(d) : "r"(a), "r"(b), "r"(c));
    return d;
}

// rows (2p,2p+1): Q.x/Q.y = row 2p cols 8l..+7, Q.z/Q.w = row 2p+1
#define DOPAIRX(p, Q, HH, HL) do {                                        \
    acch[2*(p)]   = __dp4a((int)(HH).x, (int)(Q).x, acch[2*(p)]);         \
    acch[2*(p)]   = __dp4a((int)(HH).y, (int)(Q).y, acch[2*(p)]);         \
    accl[2*(p)]   = dp4a_us((HL).x, (Q).x, accl[2*(p)]);                  \
    accl[2*(p)]   = dp4a_us((HL).y, (Q).y, accl[2*(p)]);                  \
    acch[2*(p)+1] = __dp4a((int)(HH).x, (int)(Q).z, acch[2*(p)+1]);       \
    acch[2*(p)+1] = __dp4a((int)(HH).y, (int)(Q).w, acch[2*(p)+1]);       \
    accl[2*(p)+1] = dp4a_us((HL).x, (Q).z, accl[2*(p)+1]);                \
    accl[2*(p)+1] = dp4a_us((HL).y, (Q).w, accl[2*(p)+1]);                \
} while (0)

#define LDHH(cc) (((const uint2*)hq_hi)[(cc) * 32 + lane])
#define LDHL(cc) (((const uint2*)hq_lo)[(cc) * 32 + lane])

#define DOCHUNK_SM(cc, HH, HL) do {                                       \
    const unsigned char* _c = wsm + (size_t)(cc) * CH_B + wid * 1024 + lane * 16; \
    const uint4 q0 = *(const uint4*)(_c);                                 \
    const uint4 q1 = *(const uint4*)(_c + 512);                           \
    DOPAIRX(0, q0, HH, HL); DOPAIRX(1, q1, HH, HL);                       \
} while (0)

#define DOCHUNK_SB(SB, HH, HL) do {                                       \
    DOPAIRX(0, SB[0], HH, HL); DOPAIRX(1, SB[1], HH, HL);                 \
} while (0)

#define LDSB(dst, cc) do {                                                \
    const unsigned char* _p = wsrc + (size_t)(cc) * CH_B + wid * 1024 + lane * 16; \
    dst[0] = __ldg((const uint4*)(_p));                                   \
    dst[1] = __ldg((const uint4*)(_p + 512)); } while (0)

__device__ __forceinline__ float sigf(float v) { return 1.0f / (1.0f + __expf(-v)); }

// ---------------- persistent LSTM kernel ----------------
__global__ __launch_bounds__(NTHR, 1)
void lstm_persistent_kernel(const float* __restrict__ x,
                            const float* __restrict__ w_ih,
                            const float* __restrict__ b_ih,
                            const float* __restrict__ b_hh,
                            const float* __restrict__ dense_w,
                            const float* __restrict__ dense_b,
                            float* __restrict__ out) {
    extern __shared__ unsigned char wsm[];       // 192 KB resident weights (chunks 0..5)
    __shared__ unsigned hq_hi[H / 4];            // 4 KB hi-plane (s8 bytes of h>>8)
    __shared__ unsigned hq_lo[H / 4];            // 4 KB lo-plane (u8 bytes of h&0xFF)
    __shared__ float xs[SEQ];
    __shared__ float red[NTHR / 32];

    const int tid  = threadIdx.x;
    const int lane = tid & 31;
    const int wid  = tid >> 5;                   // warp owns j = j0 + wid (all 4 gates)
    const int j0   = blockIdx.x * JPB;
    const int j    = j0 + wid;
    const unsigned char* wsrc = g_wq + (size_t)blockIdx.x * BLOCK_WQ;

    // per-lane gate constants: lane g (mod 4) holds gate g's scalars
    const int grow = (lane & 3) * H + j;
    const float wih_l  = __ldg(w_ih + grow);
    const float bsum_l = __ldg(b_ih + grow) + __ldg(b_hh + grow);
    const float scl_l  = __ldg(g_scale + grow) * (1.0f / 32767.0f);
    if (tid < SEQ) xs[tid] = x[tid];

    // copy smem-resident chunks 0..5
    {
        const uint4* gsrc = (const uint4*)wsrc;
        uint4* d = (uint4*)wsm;
        #pragma unroll
        for (int i = 0; i < SMEM_W / 16 / NTHR; ++i)
            d[tid + i * NTHR] = __ldg(gsrc + tid + i * NTHR);
    }

    const unsigned base = *(volatile unsigned*)&g_stamp[blockIdx.x];
    float c_reg = 0.0f;

    for (int t = 0; t < SEQ; ++t) {
        float dotf = 0.0f;
        if (t > 0) {
            // prefetch first three streamed chunks (independent of h)
            uint4 sb0[2], sb1[2], sb2[2];
            LDSB(sb0, 6); LDSB(sb1, 7); LDSB(sb2, 8);

            // fine-grained staging: thread waits only for ITS piece's producer,
            // then splits s16 h into hi/lo byte planes
            if (tid < 512) {
                const unsigned* sp = &g_stamp[tid >> 2];
                unsigned s;
                do {
                    asm volatile("ld.acquire.gpu.global.u32 %0, [%1];"
                                 : "=r"(s) : "l"(sp));
                } while (s - base < (unsigned)t);
                const uint4 pk = ((const uint4*)g_hq[(t - 1) & 1])[tid];
                ((uint2*)hq_hi)[tid] = make_uint2(__byte_perm(pk.x, pk.y, 0x7531),
                                                  __byte_perm(pk.z, pk.w, 0x7531));
                ((uint2*)hq_lo)[tid] = make_uint2(__byte_perm(pk.x, pk.y, 0x6420),
                                                  __byte_perm(pk.z, pk.w, 0x6420));
            }
            __syncthreads();                     // bar A: planes staged

            int acch[4] = {0, 0, 0, 0};
            int accl[4] = {0, 0, 0, 0};
            // software-pipelined h-plane loads (one chunk ahead)
            uint2 hh = LDHH(0), hl = LDHL(0), hhn, hln;
            hhn = LDHH(1);  hln = LDHL(1);  DOCHUNK_SM(0, hh, hl); hh = hhn; hl = hln;
            hhn = LDHH(2);  hln = LDHL(2);  DOCHUNK_SM(1, hh, hl); hh = hhn; hl = hln;
            hhn = LDHH(3);  hln = LDHL(3);  DOCHUNK_SM(2, hh, hl); hh = hhn; hl = hln;
            hhn = LDHH(4);  hln = LDHL(4);  DOCHUNK_SM(3, hh, hl); hh = hhn; hl = hln;
            hhn = LDHH(5);  hln = LDHL(5);  DOCHUNK_SM(4, hh, hl); hh = hhn; hl = hln;
            hhn = LDHH(6);  hln = LDHL(6);  DOCHUNK_SM(5, hh, hl); hh = hhn; hl = hln;
            hhn = LDHH(7);  hln = LDHL(7);  DOCHUNK_SB(sb0, hh, hl); LDSB(sb0, 9);  hh = hhn; hl = hln;
            hhn = LDHH(8);  hln = LDHL(8);  DOCHUNK_SB(sb1, hh, hl); LDSB(sb1, 10); hh = hhn; hl = hln;
            hhn = LDHH(9);  hln = LDHL(9);  DOCHUNK_SB(sb2, hh, hl); LDSB(sb2, 11); hh = hhn; hl = hln;
            hhn = LDHH(10); hln = LDHL(10); DOCHUNK_SB(sb0, hh, hl); LDSB(sb0, 12); hh = hhn; hl = hln;
            hhn = LDHH(11); hln = LDHL(11); DOCHUNK_SB(sb1, hh, hl); LDSB(sb1, 13); hh = hhn; hl = hln;
            hhn = LDHH(12); hln = LDHL(12); DOCHUNK_SB(sb2, hh, hl); LDSB(sb2, 14); hh = hhn; hl = hln;
            hhn = LDHH(13); hln = LDHL(13); DOCHUNK_SB(sb0, hh, hl); LDSB(sb0, 15); hh = hhn; hl = hln;
            hhn = LDHH(14); hln = LDHL(14); DOCHUNK_SB(sb1, hh, hl); hh = hhn; hl = hln;
            hhn = LDHH(15); hln = LDHL(15); DOCHUNK_SB(sb2, hh, hl); hh = hhn; hl = hln;
            DOCHUNK_SB(sb0, hh, hl);

            const int h0 = __reduce_add_sync(0xffffffffu, acch[0]);
            const int h1 = __reduce_add_sync(0xffffffffu, acch[1]);
            const int h2 = __reduce_add_sync(0xffffffffu, acch[2]);
            const int h3 = __reduce_add_sync(0xffffffffu, acch[3]);
            const int l0 = __reduce_add_sync(0xffffffffu, accl[0]);
            const int l1 = __reduce_add_sync(0xffffffffu, accl[1]);
            const int l2 = __reduce_add_sync(0xffffffffu, accl[2]);
            const int l3 = __reduce_add_sync(0xffffffffu, accl[3]);
            const int rh = (lane == 1) ? h1 : (lane == 2) ? h2 : (lane == 3) ? h3 : h0;
            const int rl = (lane == 1) ? l1 : (lane == 2) ? l2 : (lane == 3) ? l3 : l0;
            dotf = fmaf(256.0f, __int2float_rn(rh), __int2float_rn(rl)) * scl_l;
        }

        // gate-parallel tail: lanes 0..3 evaluate their gate's activation
        {
            const float xt = xs[t];
            const float v  = fmaf(wih_l, xt, bsum_l) + dotf;
            const float act = (lane == 2) ? tanhf(v) : sigf(v);
            const float a1 = __shfl_sync(0xffffffffu, act, 1);
            const float a2 = __shfl_sync(0xffffffffu, act, 2);
            const float a3 = __shfl_sync(0xffffffffu, act, 3);
            if (lane == 0) {
                const float c = a1 * c_reg + act * a2;   // sig(f)*c + sig(i)*tanh(g)
                c_reg = c;
                const float h = a3 * tanhf(c);
                ((unsigned short*)g_hq[t & 1])[j] =
                    (unsigned short)(short)__float2int_rn(h * 32767.0f);
                if (t == SEQ - 1) g_h[j] = h;
                asm volatile("membar.gl;" ::: "memory");
            }
        }
        __syncthreads();                         // bar B: all h stored+fenced
        if (tid == 0)
            *(volatile unsigned*)&g_stamp[blockIdx.x] = base + (unsigned)(t + 1);
    }

    // final sync: all blocks published h_last
    if (wid == 0) {
        const unsigned* sp = g_stamp + lane * 4;
        for (;;) {
            unsigned s0, s1, s2, s3;
            asm volatile("ld.volatile.global.v4.u32 {%0,%1,%2,%3}, [%4];"
                         : "=r"(s0), "=r"(s1), "=r"(s2), "=r"(s3) : "l"(sp));
            const bool ok = (s0 - base) >= SEQ && (s1 - base) >= SEQ
                         && (s2 - base) >= SEQ && (s3 - base) >= SEQ;
            if (__all_sync(0xffffffffu, ok)) break;
        }
        __threadfence();
    }
    __syncthreads();

    // dense epilogue: block b computes out[b] (NBLK == OUT)
    {
        const float* hw = g_h;
        const float* wr = dense_w + (size_t)blockIdx.x * H;
        float acc = 0.0f;
        #pragma unroll
        for (int k = tid; k < H; k += NTHR)
            acc += wr[k] * hw[k];
        #pragma unroll
        for (int o = 16; o > 0; o >>= 1)
            acc += __shfl_down_sync(0xffffffffu, acc, o);
        if (lane == 0) red[wid] = acc;
        __syncthreads();
        if (tid == 0) {
            float s = 0.0f;
            #pragma unroll
            for (int w = 0; w < NTHR / 32; ++w) s += red[w];
            out[blockIdx.x] = s + dense_b[blockIdx.x];
        }
    }
}

extern "C" void kernel_launch(void* const* d_in, const int* in_sizes, int n_in,
                              void* d_out, int out_size) {
    const float* x       = (const float*)d_in[0];
    const float* w_ih    = (const float*)d_in[1];
    const float* w_hh    = (const float*)d_in[2];
    const float* b_ih    = (const float*)d_in[3];
    const float* b_hh    = (const float*)d_in[4];
    const float* dense_w = (const float*)d_in[5];
    const float* dense_b = (const float*)d_in[6];

    cudaFuncSetAttribute(lstm_persistent_kernel,
                         cudaFuncAttributeMaxDynamicSharedMemorySize, SMEM_W);
    quant_kernel<<<ROWS, 256>>>(w_hh);
    lstm_persistent_kernel<<<NBLK, NTHR, SMEM_W>>>(x, w_ih, b_ih, b_hh,
                                                   dense_w, dense_b, (float*)d_out);
}